// round 5
// baseline (speedup 1.0000x reference)
#include <cuda_runtime.h>
#include <cstdint>
#include <cmath>

#define B_  256
#define T_  128
#define D_  256
#define H1  512
#define G1  (4*H1)
#define H2  1024
#define G2  (4*H2)

// Scratch (__device__ globals: allocation-free)
__device__ float g_igf [(size_t)T_*B_*G1];
__device__ float g_igb [(size_t)T_*B_*G1];
__device__ float g_igs [(size_t)T_*B_*G2];
__device__ float g_comb[(size_t)T_*B_*(2*H1)];
__device__ float g_zero[B_*H2];
__device__ float g_cf  [B_*H1];
__device__ float g_cb  [B_*H1];
__device__ float g_c2  [B_*H2];
__device__ float g_h2a [B_*H2];
__device__ float g_h2b [B_*H2];

__device__ __forceinline__ float cvt_tf32(float x) {
    uint32_t u; asm("cvt.rna.tf32.f32 %0, %1;" : "=r"(u) : "f"(x));
    return __uint_as_float(u);
}
__device__ __forceinline__ void mma_tf32(float& d0, float& d1, float& d2, float& d3,
                                         uint32_t a0, uint32_t a1, uint32_t a2, uint32_t a3,
                                         uint32_t b0, uint32_t b1) {
    asm volatile("mma.sync.aligned.m16n8k8.row.col.f32.tf32.tf32.f32 "
        "{%0,%1,%2,%3}, {%4,%5,%6,%7}, {%8,%9}, {%0,%1,%2,%3};\n"
        : "+f"(d0), "+f"(d1), "+f"(d2), "+f"(d3)
        : "r"(a0), "r"(a1), "r"(a2), "r"(a3), "r"(b0), "r"(b1));
}
__device__ __forceinline__ float sigm_(float x) { return 1.0f / (1.0f + expf(-x)); }

// out[orow(m)][n] = sum_k A[m][k]*W[n][k].  remap: 0 identity; 1 fwd time-major; 2 reversed.
__global__ void __launch_bounds__(256, 2) gemm_tf32_nt(
    const float* __restrict__ A, const float* __restrict__ W,
    float* __restrict__ out, int M, int N, int K, int remap)
{
    constexpr int BM = 128, BN = 64, BK = 32;
    __shared__ float As[BM][BK + 1];
    __shared__ float Bs[BN][BK + 1];
    const int tid = threadIdx.x, lane = tid & 31, warp = tid >> 5;
    const int gid = lane >> 2, tig = lane & 3;
    const int wm = warp >> 1, wn = warp & 1;
    const int bm0 = blockIdx.y * BM, bn0 = blockIdx.x * BN;

    float acc[2][4][4];
#pragma unroll
    for (int a = 0; a < 2; a++)
#pragma unroll
        for (int b = 0; b < 4; b++)
#pragma unroll
            for (int c = 0; c < 4; c++) acc[a][b][c] = 0.f;

    const int kIters = K / BK;
    float4 pa[4], pb[2];
#pragma unroll
    for (int j = 0; j < 4; j++) { int i = tid + j*256, r = i>>3, c = i&7;
        pa[j] = *(const float4*)(A + (size_t)(bm0+r)*K + c*4); }
#pragma unroll
    for (int j = 0; j < 2; j++) { int i = tid + j*256, r = i>>3, c = i&7;
        pb[j] = *(const float4*)(W + (size_t)(bn0+r)*K + c*4); }

    for (int kt = 0; kt < kIters; kt++) {
#pragma unroll
        for (int j = 0; j < 4; j++) { int i = tid + j*256, r = i>>3, c = i&7;
            As[r][c*4+0]=cvt_tf32(pa[j].x); As[r][c*4+1]=cvt_tf32(pa[j].y);
            As[r][c*4+2]=cvt_tf32(pa[j].z); As[r][c*4+3]=cvt_tf32(pa[j].w); }
#pragma unroll
        for (int j = 0; j < 2; j++) { int i = tid + j*256, r = i>>3, c = i&7;
            Bs[r][c*4+0]=cvt_tf32(pb[j].x); Bs[r][c*4+1]=cvt_tf32(pb[j].y);
            Bs[r][c*4+2]=cvt_tf32(pb[j].z); Bs[r][c*4+3]=cvt_tf32(pb[j].w); }
        __syncthreads();
        if (kt + 1 < kIters) {
            int k0 = (kt+1)*BK;
#pragma unroll
            for (int j = 0; j < 4; j++) { int i = tid + j*256, r = i>>3, c = i&7;
                pa[j] = *(const float4*)(A + (size_t)(bm0+r)*K + k0 + c*4); }
#pragma unroll
            for (int j = 0; j < 2; j++) { int i = tid + j*256, r = i>>3, c = i&7;
                pb[j] = *(const float4*)(W + (size_t)(bn0+r)*K + k0 + c*4); }
        }
#pragma unroll
        for (int kc = 0; kc < BK/8; kc++) {
            uint32_t af[2][4];
#pragma unroll
            for (int mt = 0; mt < 2; mt++) {
                int r = wm*32 + mt*16;
                af[mt][0] = __float_as_uint(As[r+gid  ][kc*8+tig  ]);
                af[mt][1] = __float_as_uint(As[r+gid+8][kc*8+tig  ]);
                af[mt][2] = __float_as_uint(As[r+gid  ][kc*8+tig+4]);
                af[mt][3] = __float_as_uint(As[r+gid+8][kc*8+tig+4]);
            }
#pragma unroll
            for (int nt = 0; nt < 4; nt++) {
                int cc = wn*32 + nt*8;
                uint32_t b0 = __float_as_uint(Bs[cc+gid][kc*8+tig  ]);
                uint32_t b1 = __float_as_uint(Bs[cc+gid][kc*8+tig+4]);
#pragma unroll
                for (int mt = 0; mt < 2; mt++)
                    mma_tf32(acc[mt][nt][0],acc[mt][nt][1],acc[mt][nt][2],acc[mt][nt][3],
                             af[mt][0],af[mt][1],af[mt][2],af[mt][3], b0, b1);
            }
        }
        __syncthreads();
    }
#pragma unroll
    for (int mt = 0; mt < 2; mt++)
#pragma unroll
        for (int half = 0; half < 2; half++) {
            int m = bm0 + wm*32 + mt*16 + gid + half*8;
            int orow;
            if (remap == 0) orow = m;
            else { int t = m % T_, b = m / T_;
                   orow = ((remap == 1) ? t : (T_-1-t)) * B_ + b; }
            float* op = out + (size_t)orow*N + bn0 + wn*32 + 2*tig;
#pragma unroll
            for (int nt = 0; nt < 4; nt++) {
                op[nt*8+0] = acc[mt][nt][half*2+0];
                op[nt*8+1] = acc[mt][nt][half*2+1];
            }
        }
}

// One LSTM step: block = 64 batch x 32 hidden; 4 warps = 4 gates. z-dim = direction.
template <int HD>
__global__ void __launch_bounds__(128, 1) lstm_step(
    const float* __restrict__ Whh_f, const float* __restrict__ Whh_b,
    const float* __restrict__ bias_f, const float* __restrict__ bias_b,
    const float* __restrict__ igf, const float* __restrict__ igb,
    float* __restrict__ c_f, float* __restrict__ c_b,
    const float* __restrict__ hprev, int hp_stride, int hp_diroff,
    float* __restrict__ hnext, int hn_stride, int hn_diroff, int step)
{
    constexpr int BMs = 64, BJ = 32, BKs = 16;
    __shared__ float As[BMs][BKs + 1];
    __shared__ float Bs[4*BJ][BKs + 1];
    __shared__ float gsh[BMs][4*BJ + 1];

    const int dir = blockIdx.z;
    const float* Whh  = dir ? Whh_b  : Whh_f;
    const float* bias = dir ? bias_b : bias_f;
    const float* ig   = dir ? igb    : igf;
    float*       cbuf = dir ? c_b    : c_f;

    const int m0 = blockIdx.x * BMs, j0 = blockIdx.y * BJ;
    const int tid = threadIdx.x, lane = tid & 31, warp = tid >> 5;
    const int gid = lane >> 2, tig = lane & 3;
    const float* hp = hprev + dir * hp_diroff;

    float acc[4][4][4];
#pragma unroll
    for (int a = 0; a < 4; a++)
#pragma unroll
        for (int b = 0; b < 4; b++)
#pragma unroll
            for (int c = 0; c < 4; c++) acc[a][b][c] = 0.f;

    const int kIters = HD / BKs;
    float4 pa[2], pb[4];
#pragma unroll
    for (int j = 0; j < 2; j++) { int i = tid + j*128, r = i>>2, c = i&3;
        pa[j] = *(const float4*)(hp + (size_t)(m0+r)*hp_stride + c*4); }
#pragma unroll
    for (int j = 0; j < 4; j++) { int i = tid + j*128, n = i>>2, c = i&3;
        int grow = (n>>5)*HD + j0 + (n&31);
        pb[j] = *(const float4*)(Whh + (size_t)grow*HD + c*4); }

    for (int kt = 0; kt < kIters; kt++) {
#pragma unroll
        for (int j = 0; j < 2; j++) { int i = tid + j*128, r = i>>2, c = i&3;
            As[r][c*4+0]=cvt_tf32(pa[j].x); As[r][c*4+1]=cvt_tf32(pa[j].y);
            As[r][c*4+2]=cvt_tf32(pa[j].z); As[r][c*4+3]=cvt_tf32(pa[j].w); }
#pragma unroll
        for (int j = 0; j < 4; j++) { int i = tid + j*128, n = i>>2, c = i&3;
            Bs[n][c*4+0]=cvt_tf32(pb[j].x); Bs[n][c*4+1]=cvt_tf32(pb[j].y);
            Bs[n][c*4+2]=cvt_tf32(pb[j].z); Bs[n][c*4+3]=cvt_tf32(pb[j].w); }
        __syncthreads();
        if (kt + 1 < kIters) {
            int k0 = (kt+1)*BKs;
#pragma unroll
            for (int j = 0; j < 2; j++) { int i = tid + j*128, r = i>>2, c = i&3;
                pa[j] = *(const float4*)(hp + (size_t)(m0+r)*hp_stride + k0 + c*4); }
#pragma unroll
            for (int j = 0; j < 4; j++) { int i = tid + j*128, n = i>>2, c = i&3;
                int grow = (n>>5)*HD + j0 + (n&31);
                pb[j] = *(const float4*)(Whh + (size_t)grow*HD + k0 + c*4); }
        }
#pragma unroll
        for (int kc = 0; kc < 2; kc++) {
            uint32_t af[4][4];
#pragma unroll
            for (int mt = 0; mt < 4; mt++) {
                int r = mt*16;
                af[mt][0] = __float_as_uint(As[r+gid  ][kc*8+tig  ]);
                af[mt][1] = __float_as_uint(As[r+gid+8][kc*8+tig  ]);
                af[mt][2] = __float_as_uint(As[r+gid  ][kc*8+tig+4]);
                af[mt][3] = __float_as_uint(As[r+gid+8][kc*8+tig+4]);
            }
#pragma unroll
            for (int nt = 0; nt < 4; nt++) {
                int br = warp*BJ + nt*8 + gid;
                uint32_t b0 = __float_as_uint(Bs[br][kc*8+tig  ]);
                uint32_t b1 = __float_as_uint(Bs[br][kc*8+tig+4]);
#pragma unroll
                for (int mt = 0; mt < 4; mt++)
                    mma_tf32(acc[mt][nt][0],acc[mt][nt][1],acc[mt][nt][2],acc[mt][nt][3],
                             af[mt][0],af[mt][1],af[mt][2],af[mt][3], b0, b1);
            }
        }
        __syncthreads();
    }

#pragma unroll
    for (int mt = 0; mt < 4; mt++)
#pragma unroll
        for (int nt = 0; nt < 4; nt++) {
            int col = warp*BJ + nt*8 + 2*tig;
            gsh[mt*16+gid  ][col  ] = acc[mt][nt][0];
            gsh[mt*16+gid  ][col+1] = acc[mt][nt][1];
            gsh[mt*16+gid+8][col  ] = acc[mt][nt][2];
            gsh[mt*16+gid+8][col+1] = acc[mt][nt][3];
        }
    __syncthreads();

    for (int i = tid; i < BMs*BJ; i += 128) {
        int row = i >> 5, jj = i & 31;
        int b = m0 + row, j = j0 + jj;
        size_t igbase = ((size_t)step*B_ + b) * (size_t)(4*HD);
        float gi = gsh[row][       jj] + ig[igbase + 0*HD + j] + bias[0*HD + j];
        float gf = gsh[row][  BJ + jj] + ig[igbase + 1*HD + j] + bias[1*HD + j];
        float gg = gsh[row][2*BJ + jj] + ig[igbase + 2*HD + j] + bias[2*HD + j];
        float go = gsh[row][3*BJ + jj] + ig[igbase + 3*HD + j] + bias[3*HD + j];
        float cold = cbuf[(size_t)b*HD + j];
        float cn = sigm_(gf)*cold + sigm_(gi)*tanhf(gg);
        cbuf[(size_t)b*HD + j] = cn;
        hnext[(size_t)b*hn_stride + dir*hn_diroff + j] = sigm_(go)*tanhf(cn);
    }
}

__global__ void classifier_kernel(const float* __restrict__ h, const float* __restrict__ Wl,
                                  const float* __restrict__ bl, float* __restrict__ out)
{
    int wid = (blockIdx.x * blockDim.x + threadIdx.x) >> 5;
    int lane = threadIdx.x & 31;
    if (wid >= B_) return;
    const float* hb = h + (size_t)wid * H2;
    float s0 = 0.f, s1 = 0.f;
    for (int j = lane*4; j < H2; j += 128) {
        float4 hv = *(const float4*)(hb + j);
        float4 w0 = *(const float4*)(Wl + j);
        float4 w1 = *(const float4*)(Wl + H2 + j);
        s0 += hv.x*w0.x + hv.y*w0.y + hv.z*w0.z + hv.w*w0.w;
        s1 += hv.x*w1.x + hv.y*w1.y + hv.z*w1.z + hv.w*w1.w;
    }
#pragma unroll
    for (int o = 16; o > 0; o >>= 1) {
        s0 += __shfl_down_sync(0xFFFFFFFFu, s0, o);
        s1 += __shfl_down_sync(0xFFFFFFFFu, s1, o);
    }
    if (lane == 0) {
        out[wid*2+0] = sigm_(s0 + bl[0]);
        out[wid*2+1] = sigm_(s1 + bl[1]);
    }
}

extern "C" void kernel_launch(void* const* d_in, const int* in_sizes, int n_in,
                              void* d_out, int out_size)
{
    (void)in_sizes; (void)n_in; (void)out_size;
    const float* x     = (const float*)d_in[0];
    const float* Wf_ih = (const float*)d_in[1];
    const float* Wf_hh = (const float*)d_in[2];
    const float* bf    = (const float*)d_in[3];
    const float* Wb_ih = (const float*)d_in[4];
    const float* Wb_hh = (const float*)d_in[5];
    const float* bb    = (const float*)d_in[6];
    const float* Ws_ih = (const float*)d_in[7];
    const float* Ws_hh = (const float*)d_in[8];
    const float* bs    = (const float*)d_in[9];
    const float* Wl    = (const float*)d_in[10];
    const float* bl    = (const float*)d_in[11];
    float* out = (float*)d_out;

    float *p_igf,*p_igb,*p_igs,*p_comb,*p_zero,*p_cf,*p_cb,*p_c2,*p_h2a,*p_h2b;
    cudaGetSymbolAddress((void**)&p_igf,  g_igf);
    cudaGetSymbolAddress((void**)&p_igb,  g_igb);
    cudaGetSymbolAddress((void**)&p_igs,  g_igs);
    cudaGetSymbolAddress((void**)&p_comb, g_comb);
    cudaGetSymbolAddress((void**)&p_zero, g_zero);
    cudaGetSymbolAddress((void**)&p_cf,   g_cf);
    cudaGetSymbolAddress((void**)&p_cb,   g_cb);
    cudaGetSymbolAddress((void**)&p_c2,   g_c2);
    cudaGetSymbolAddress((void**)&p_h2a,  g_h2a);
    cudaGetSymbolAddress((void**)&p_h2b,  g_h2b);

    cudaMemsetAsync(p_zero, 0, (size_t)B_*H2*sizeof(float));
    cudaMemsetAsync(p_cf,   0, (size_t)B_*H1*sizeof(float));
    cudaMemsetAsync(p_cb,   0, (size_t)B_*H1*sizeof(float));
    cudaMemsetAsync(p_c2,   0, (size_t)B_*H2*sizeof(float));

    // Input projections (time-independent): remap rows to [t][b] (bwd reversed).
    gemm_tf32_nt<<<dim3(G1/64, (B_*T_)/128), 256>>>(x, Wf_ih, p_igf, B_*T_, G1, D_, 1);
    gemm_tf32_nt<<<dim3(G1/64, (B_*T_)/128), 256>>>(x, Wb_ih, p_igb, B_*T_, G1, D_, 2);

    // BiLSTM layer 1: both directions per step; h written into comb buffer.
    for (int t = 0; t < T_; t++) {
        const float* hp = (t == 0) ? p_zero : p_comb + (size_t)(t-1)*B_*(2*H1);
        lstm_step<H1><<<dim3(B_/64, H1/32, 2), 128>>>(
            Wf_hh, Wb_hh, bf, bb, p_igf, p_igb, p_cf, p_cb,
            hp, 2*H1, H1, p_comb + (size_t)t*B_*(2*H1), 2*H1, H1, t);
    }

    // Input projection for LSTM2 over the full combined sequence.
    gemm_tf32_nt<<<dim3(G2/64, (B_*T_)/128), 256>>>(p_comb, Ws_ih, p_igs, B_*T_, G2, 2*H1, 0);

    // LSTM layer 2 (only final h needed, but scan is sequential).
    for (int t = 0; t < T_; t++) {
        const float* hp = (t == 0) ? p_zero : (((t-1)&1) ? p_h2b : p_h2a);
        float* hn = (t & 1) ? p_h2b : p_h2a;
        lstm_step<H2><<<dim3(B_/64, H2/32, 1), 128>>>(
            Ws_hh, Ws_hh, bs, bs, p_igs, p_igs, p_c2, p_c2,
            hp, H2, 0, hn, H2, 0, t);
    }

    classifier_kernel<<<32, 256>>>(p_h2b, Wl, bl, out);
}